// round 1
// baseline (speedup 1.0000x reference)
#include <cuda_runtime.h>
#include <math.h>

#define BSZ 16
#define NC  1024
#define NT  2048
#define NTT (BSZ*NT)    // 32768 targets total
#define XD  8
#define HID 256
#define HH  128
#define DD  384
#define NE  4

// ---------------- scratch (device globals; no runtime allocation) ----------------
__device__ float g_enc3[BSZ*HID];
__device__ float g_z  [(size_t)NTT*512];   // [enc3 | moe_out]
__device__ float g_fh [(size_t)NTT*HH];    // relu(z@Wfps1+b)
__device__ float g_zd [(size_t)NTT*DD];    // [t_attr | r]
__device__ float g_gd [(size_t)NTT*NE];    // decoder gate
__device__ float g_zd2[(size_t)NTT*DD];    // decoder MoE out
__device__ float g_h1 [(size_t)NTT*HID];
__device__ float g_h2 [(size_t)NTT*HID];

// ---------------- enc3: mean-pooled deterministic encoder (tiny) ----------------
__global__ __launch_bounds__(256) void enc3_kernel(
    const float* __restrict__ cx, const float* __restrict__ cy,
    const float* __restrict__ Wp, const float* __restrict__ bp,
    const float* __restrict__ Wl, const float* __restrict__ bl)
{
    __shared__ float red[256*9];
    __shared__ float h0[HID];
    int b = blockIdx.x, tid = threadIdx.x;
    float l[9];
    #pragma unroll
    for (int x = 0; x < 9; x++) l[x] = 0.f;
    for (int c = tid; c < NC; c += 256) {
        #pragma unroll
        for (int x = 0; x < XD; x++) l[x] += cx[((size_t)b*NC + c)*XD + x];
        l[8] += cy[b*NC + c];
    }
    #pragma unroll
    for (int x = 0; x < 9; x++) red[tid*9 + x] = l[x];
    __syncthreads();
    for (int s = 128; s; s >>= 1) {
        if (tid < s) {
            #pragma unroll
            for (int x = 0; x < 9; x++) red[tid*9 + x] += red[(tid+s)*9 + x];
        }
        __syncthreads();
    }
    // mean cxy @ W_proj3 + b  (exact: mean commutes with the affine map)
    {
        int h = tid;
        float a = bp[h];
        #pragma unroll
        for (int x = 0; x < 9; x++) a = fmaf(red[x]*(1.f/NC), Wp[x*HID + h], a);
        h0[h] = a;
    }
    __syncthreads();
    {
        int h = tid;
        float a = bl[h];
        for (int k = 0; k < HID; k++) a = fmaf(h0[k], Wl[k*HID + h], a);
        g_enc3[b*HID + h] = a;
    }
}

// ---------------- per-target: similarity aggregation + enc-MoE + t_attr ----------------
// One warp per target (16 targets/warp). Context tile (coords+y, padded to 9 -> bank-conflict-free)
// and all small encoder weights live in smem.
__global__ __launch_bounds__(256) void target_kernel(
    const float* __restrict__ cx, const float* __restrict__ cy,
    const float* __restrict__ txg,
    const float* __restrict__ Wee, const float* __restrict__ bee,
    const float* __restrict__ Wge, const float* __restrict__ bge,
    const float* __restrict__ Wat, const float* __restrict__ bat)
{
    extern __shared__ float sm[];
    float* sc  = sm;                  // NC*9
    float* sWe = sc  + NC*9;          // 4*9*256
    float* sbe = sWe + NE*9*HID;      // 4*256
    float* sWa = sbe + NE*HID;        // 8*128
    float* sba = sWa + XD*HH;         // 128
    float* sWg = sba + HH;            // 32
    float* sbg = sWg + XD*NE;         // 4

    int b  = blockIdx.x >> 4;
    int t0 = (blockIdx.x & 15) << 7;
    int tid = threadIdx.x;

    for (int i = tid; i < NC*XD; i += 256) sc[(i>>3)*9 + (i&7)] = cx[(size_t)b*NC*XD + i];
    for (int i = tid; i < NC;    i += 256) sc[i*9 + 8] = cy[b*NC + i];
    for (int i = tid; i < NE*9*HID; i += 256) sWe[i] = Wee[i];
    for (int i = tid; i < NE*HID;   i += 256) sbe[i] = bee[i];
    for (int i = tid; i < XD*HH;    i += 256) sWa[i] = Wat[i];
    if (tid < HH)    sba[tid] = bat[tid];
    if (tid < XD*NE) sWg[tid] = Wge[tid];
    if (tid < NE)    sbg[tid] = bge[tid];
    __syncthreads();

    int warp = tid >> 5, lane = tid & 31;
    for (int tt = warp; tt < 128; tt += 8) {
        int t = t0 + tt;
        size_t gt = (size_t)b*NT + t;
        float tx[XD];
        #pragma unroll
        for (int x = 0; x < XD; x++) tx[x] = txg[gt*XD + x];

        float acc[10];
        #pragma unroll
        for (int i = 0; i < 10; i++) acc[i] = 0.f;
        for (int c = lane; c < NC; c += 32) {
            const float* p = &sc[c*9];
            float d2 = 1e-12f;
            #pragma unroll
            for (int x = 0; x < XD; x++) { float d = tx[x]-p[x]; d2 = fmaf(d, d, d2); }
            float dist = d2 * __frsqrt_rn(d2);          // sqrt(d2), d2 >= 1e-12
            float w = __expf(-dist);                    // laplace kernel
            acc[9] += w;
            #pragma unroll
            for (int x = 0; x < 9; x++) acc[x] = fmaf(w, p[x], acc[x]);
        }
        #pragma unroll
        for (int o = 16; o; o >>= 1) {
            #pragma unroll
            for (int i = 0; i < 10; i++) acc[i] += __shfl_xor_sync(0xffffffffu, acc[i], o);
        }
        float inv = 1.f/acc[9];
        float s[9];
        #pragma unroll
        for (int x = 0; x < 9; x++) s[x] = acc[x]*inv;

        // encoder gate (softmax over 4 experts)
        float g[NE];
        #pragma unroll
        for (int e = 0; e < NE; e++) {
            float a = sbg[e];
            #pragma unroll
            for (int x = 0; x < XD; x++) a = fmaf(tx[x], sWg[x*NE + e], a);
            g[e] = a;
        }
        float gm = fmaxf(fmaxf(g[0],g[1]), fmaxf(g[2],g[3]));
        float gs = 0.f;
        #pragma unroll
        for (int e = 0; e < NE; e++) { g[e] = __expf(g[e]-gm); gs += g[e]; }
        float gi = 1.f/gs;
        #pragma unroll
        for (int e = 0; e < NE; e++) g[e] *= gi;

        // moe_out[h] = sum_e g_e (s . W_e[:,h] + b_e[h]);  write z = [enc3 | moe_out]
        #pragma unroll
        for (int j = 0; j < 8; j++) {
            int h = lane + 32*j;
            float o2 = 0.f;
            #pragma unroll
            for (int e = 0; e < NE; e++) {
                float a = sbe[e*HID + h];
                #pragma unroll
                for (int x = 0; x < 9; x++) a = fmaf(s[x], sWe[(e*9 + x)*HID + h], a);
                o2 = fmaf(g[e], a, o2);
            }
            g_z[gt*512 + 256 + h] = o2;
            g_z[gt*512 + h] = g_enc3[b*HID + h];
        }
        // t_attr -> zd[:, 0:128]
        #pragma unroll
        for (int j = 0; j < 4; j++) {
            int h = lane + 32*j;
            float a = sba[h];
            #pragma unroll
            for (int x = 0; x < XD; x++) a = fmaf(tx[x], sWa[x*HH + h], a);
            g_zd[gt*DD + h] = a;
        }
    }
}

// ---------------- generic tiled fp32 GEMM: C[M,N] = act(A[M,K] @ B[K,N] + bias) ----------------
// EXPERTS=1: C = sum_e gate[row,e] * (A @ B_e + bias_e)  (decoder MoE, B = (4,K,N) stacked)
template<int RELU, int EXPERTS>
__global__ __launch_bounds__(256) void gemm_kernel(
    const float* __restrict__ A, const float* __restrict__ B,
    const float* __restrict__ bias, float* __restrict__ C,
    int N, int K, int ldc, int coff)
{
    __shared__ float As[16][128];
    __shared__ float Bs[16][64];
    int tid = threadIdx.x;
    int m0 = blockIdx.x*128, n0 = blockIdx.y*64;
    int trow = (tid >> 4) << 3;     // 8 rows
    int tcol = (tid & 15) << 2;     // 4 cols

    float accF[8][4];
    #pragma unroll
    for (int i = 0; i < 8; i++)
        #pragma unroll
        for (int j = 0; j < 4; j++) accF[i][j] = 0.f;

    const int nexp = EXPERTS ? 4 : 1;
    for (int e = 0; e < nexp; e++) {
        const float* Be = B + (size_t)e*K*N;
        float acc[8][4];
        #pragma unroll
        for (int i = 0; i < 8; i++)
            #pragma unroll
            for (int j = 0; j < 4; j++) acc[i][j] = 0.f;

        for (int k0 = 0; k0 < K; k0 += 16) {
            #pragma unroll
            for (int v = 0; v < 2; v++) {
                int slot = tid + v*256;
                int m = slot >> 2, kq = (slot & 3) << 2;
                float4 a4 = *(const float4*)&A[(size_t)(m0+m)*K + k0 + kq];
                As[kq+0][m] = a4.x; As[kq+1][m] = a4.y;
                As[kq+2][m] = a4.z; As[kq+3][m] = a4.w;
            }
            {
                int kr = tid >> 4, nq = (tid & 15) << 2;
                *(float4*)&Bs[kr][nq] = *(const float4*)&Be[(size_t)(k0+kr)*N + n0 + nq];
            }
            __syncthreads();
            #pragma unroll
            for (int kk = 0; kk < 16; kk++) {
                float4 b4 = *(float4*)&Bs[kk][tcol];
                #pragma unroll
                for (int i = 0; i < 8; i++) {
                    float a = As[kk][trow + i];
                    acc[i][0] = fmaf(a, b4.x, acc[i][0]);
                    acc[i][1] = fmaf(a, b4.y, acc[i][1]);
                    acc[i][2] = fmaf(a, b4.z, acc[i][2]);
                    acc[i][3] = fmaf(a, b4.w, acc[i][3]);
                }
            }
            __syncthreads();
        }
        #pragma unroll
        for (int i = 0; i < 8; i++) {
            float gw = EXPERTS ? g_gd[(size_t)(m0 + trow + i)*4 + e] : 1.f;
            #pragma unroll
            for (int j = 0; j < 4; j++) {
                float bb = EXPERTS ? bias[e*N + n0 + tcol + j] : bias[n0 + tcol + j];
                accF[i][j] = fmaf(gw, acc[i][j] + bb, accF[i][j]);
            }
        }
    }
    #pragma unroll
    for (int i = 0; i < 8; i++) {
        size_t row = (size_t)(m0 + trow + i);
        float4 o;
        o.x = accF[i][0]; o.y = accF[i][1]; o.z = accF[i][2]; o.w = accF[i][3];
        if (RELU) {
            o.x = fmaxf(o.x, 0.f); o.y = fmaxf(o.y, 0.f);
            o.z = fmaxf(o.z, 0.f); o.w = fmaxf(o.w, 0.f);
        }
        *(float4*)&C[row*ldc + coff + n0 + tcol] = o;
    }
}

// ---------------- decoder gate: softmax(zd @ Wg + bg), warp per target ----------------
__global__ __launch_bounds__(256) void decgate_kernel(
    const float* __restrict__ Wg, const float* __restrict__ bg)
{
    int warp = threadIdx.x >> 5, lane = threadIdx.x & 31;
    size_t gt = (size_t)blockIdx.x*8 + warp;
    float a0=0.f, a1=0.f, a2=0.f, a3=0.f;
    const float4* W4 = (const float4*)Wg;
    for (int k = lane; k < DD; k += 32) {
        float z = g_zd[gt*DD + k];
        float4 w = W4[k];
        a0 = fmaf(z, w.x, a0); a1 = fmaf(z, w.y, a1);
        a2 = fmaf(z, w.z, a2); a3 = fmaf(z, w.w, a3);
    }
    #pragma unroll
    for (int o = 16; o; o >>= 1) {
        a0 += __shfl_xor_sync(0xffffffffu, a0, o);
        a1 += __shfl_xor_sync(0xffffffffu, a1, o);
        a2 += __shfl_xor_sync(0xffffffffu, a2, o);
        a3 += __shfl_xor_sync(0xffffffffu, a3, o);
    }
    a0 += bg[0]; a1 += bg[1]; a2 += bg[2]; a3 += bg[3];
    float m = fmaxf(fmaxf(a0,a1), fmaxf(a2,a3));
    float e0 = __expf(a0-m), e1 = __expf(a1-m), e2 = __expf(a2-m), e3 = __expf(a3-m);
    float inv = 1.f/(e0+e1+e2+e3);
    if (lane == 0) {
        g_gd[gt*4+0] = e0*inv; g_gd[gt*4+1] = e1*inv;
        g_gd[gt*4+2] = e2*inv; g_gd[gt*4+3] = e3*inv;
    }
}

// ---------------- head: h2 @ W_d3 + b -> mu, sigma ----------------
__global__ __launch_bounds__(256) void head_kernel(
    const float* __restrict__ W3, const float* __restrict__ b3, float* __restrict__ out)
{
    int warp = threadIdx.x >> 5, lane = threadIdx.x & 31;
    size_t gt = (size_t)blockIdx.x*8 + warp;
    float a0=0.f, a1=0.f;
    const float2* W2 = (const float2*)W3;
    for (int k = lane; k < HID; k += 32) {
        float h = g_h2[gt*HID + k];
        float2 w = W2[k];
        a0 = fmaf(h, w.x, a0); a1 = fmaf(h, w.y, a1);
    }
    #pragma unroll
    for (int o = 16; o; o >>= 1) {
        a0 += __shfl_xor_sync(0xffffffffu, a0, o);
        a1 += __shfl_xor_sync(0xffffffffu, a1, o);
    }
    if (lane == 0) {
        float mu = a0 + b3[0];
        float x  = a1 + b3[1];
        float sp = fmaxf(x, 0.f) + log1pf(__expf(-fabsf(x)));  // stable softplus
        out[gt]       = mu;
        out[NTT + gt] = 0.1f + 0.9f*sp;
    }
}

// ---------------- Moran k-NN lag: one selection pass serves both y and mu ----------------
__global__ __launch_bounds__(256) void moran_kernel(
    const float* __restrict__ txg, const float* __restrict__ tyg, float* __restrict__ out)
{
    extern __shared__ float sm[];
    float* st  = sm;            // NT*9 : coords[8] + norm2
    float* sy  = st + NT*9;     // NT
    float* smu = sy + NT;       // NT
    int b  = blockIdx.x >> 4;
    int t0 = (blockIdx.x & 15) << 7;
    int tid = threadIdx.x;

    for (int i = tid; i < NT*XD; i += 256) st[(i>>3)*9 + (i&7)] = txg[(size_t)b*NT*XD + i];
    for (int i = tid; i < NT; i += 256) { sy[i] = tyg[b*NT + i]; smu[i] = out[b*NT + i]; }
    __syncthreads();
    for (int i = tid; i < NT; i += 256) {
        float n = 0.f;
        #pragma unroll
        for (int x = 0; x < XD; x++) { float v = st[i*9 + x]; n = fmaf(v, v, n); }
        st[i*9 + 8] = n;
    }
    __syncthreads();

    int warp = tid >> 5, lane = tid & 31;
    for (int tt = warp; tt < 128; tt += 8) {
        int t = t0 + tt;
        float tx[XD];
        #pragma unroll
        for (int x = 0; x < XD; x++) tx[x] = st[t*9 + x];
        float tn = st[t*9 + 8];

        float bd0=INFINITY,bd1=INFINITY,bd2=INFINITY,bd3=INFINITY,bd4=INFINITY;
        int   bi0=0,bi1=0,bi2=0,bi3=0,bi4=0;
        for (int c = lane; c < NT; c += 32) {
            if (c == t) continue;
            const float* p = &st[c*9];
            float dot = 0.f;
            #pragma unroll
            for (int x = 0; x < XD; x++) dot = fmaf(tx[x], p[x], dot);
            float d2 = tn + p[8] - 2.f*dot;            // reference's expansion formula
            d2 = fmaxf(d2, 0.f) + 1e-12f;
            if (d2 < bd4) {
                bd4 = d2; bi4 = c;
                if (bd4 < bd3) { float td=bd3; bd3=bd4; bd4=td; int ti=bi3; bi3=bi4; bi4=ti; }
                if (bd3 < bd2) { float td=bd2; bd2=bd3; bd3=td; int ti=bi2; bi2=bi3; bi3=ti; }
                if (bd2 < bd1) { float td=bd1; bd1=bd2; bd2=td; int ti=bi1; bi1=bi2; bi2=ti; }
                if (bd1 < bd0) { float td=bd0; bd0=bd1; bd1=td; int ti=bi0; bi0=bi1; bi1=ti; }
            }
        }
        // warp merge: 5 rounds of argmin (tie -> lower index, matching stable top_k)
        float seld[5]; int seli[5];
        #pragma unroll
        for (int r = 0; r < 5; r++) {
            float rd = bd0; int ri = bi0; int rl = lane;
            #pragma unroll
            for (int o = 16; o; o >>= 1) {
                float od = __shfl_xor_sync(0xffffffffu, rd, o);
                int   oi = __shfl_xor_sync(0xffffffffu, ri, o);
                int   ol = __shfl_xor_sync(0xffffffffu, rl, o);
                if (od < rd || (od == rd && oi < ri)) { rd = od; ri = oi; rl = ol; }
            }
            seld[r] = rd; seli[r] = ri;
            if (lane == rl) {
                bd0=bd1; bi0=bi1; bd1=bd2; bi1=bi2; bd2=bd3; bi2=bi3;
                bd3=bd4; bi3=bi4; bd4=INFINITY; bi4=0x7fffffff;
            }
        }
        if (lane == 0) {
            float w[5], ws = 0.f;
            #pragma unroll
            for (int r = 0; r < 5; r++) { w[r] = __expf(-0.1f*sqrtf(seld[r])); ws += w[r]; }
            float inv = 1.f/ws;
            float ly = 0.f, lm = 0.f;
            #pragma unroll
            for (int r = 0; r < 5; r++) {
                float wr = w[r]*inv;
                ly = fmaf(wr, sy[seli[r]],  ly);
                lm = fmaf(wr, smu[seli[r]], lm);
            }
            size_t gt = (size_t)b*NT + t;
            out[2*(size_t)NTT + gt] = ly;
            out[3*(size_t)NTT + gt] = lm;
        }
    }
}

// ---------------- launch ----------------
extern "C" void kernel_launch(void* const* d_in, const int* in_sizes, int n_in,
                              void* d_out, int out_size)
{
    const float* cx   = (const float*)d_in[0];
    const float* cy   = (const float*)d_in[1];
    const float* txp  = (const float*)d_in[2];
    const float* typ  = (const float*)d_in[3];
    const float* Wge  = (const float*)d_in[4];
    const float* bge  = (const float*)d_in[5];
    const float* Wee  = (const float*)d_in[6];
    const float* bee  = (const float*)d_in[7];
    const float* Wp3  = (const float*)d_in[8];
    const float* bp3  = (const float*)d_in[9];
    const float* Wlin = (const float*)d_in[10];
    const float* blin = (const float*)d_in[11];
    const float* Wf1  = (const float*)d_in[12];
    const float* bf1  = (const float*)d_in[13];
    const float* Wf2  = (const float*)d_in[14];
    const float* bf2  = (const float*)d_in[15];
    const float* Wat  = (const float*)d_in[16];
    const float* bat  = (const float*)d_in[17];
    const float* Wgd  = (const float*)d_in[18];
    const float* bgd  = (const float*)d_in[19];
    const float* Wed  = (const float*)d_in[20];
    const float* bed  = (const float*)d_in[21];
    const float* Wd1  = (const float*)d_in[22];
    const float* bd1  = (const float*)d_in[23];
    const float* Wd2  = (const float*)d_in[24];
    const float* bd2  = (const float*)d_in[25];
    const float* Wd3  = (const float*)d_in[26];
    const float* bd3  = (const float*)d_in[27];
    float* out = (float*)d_out;

    float *p_z, *p_fh, *p_zd, *p_zd2, *p_h1, *p_h2;
    cudaGetSymbolAddress((void**)&p_z,   g_z);
    cudaGetSymbolAddress((void**)&p_fh,  g_fh);
    cudaGetSymbolAddress((void**)&p_zd,  g_zd);
    cudaGetSymbolAddress((void**)&p_zd2, g_zd2);
    cudaGetSymbolAddress((void**)&p_h1,  g_h1);
    cudaGetSymbolAddress((void**)&p_h2,  g_h2);

    const int smem_t = (NC*9 + NE*9*HID + NE*HID + XD*HH + HH + XD*NE + NE)*4;  // ~82.6 KB
    const int smem_m = (NT*9 + NT + NT)*4;                                      // ~88 KB
    cudaFuncSetAttribute(target_kernel, cudaFuncAttributeMaxDynamicSharedMemorySize, smem_t);
    cudaFuncSetAttribute(moran_kernel,  cudaFuncAttributeMaxDynamicSharedMemorySize, smem_m);

    enc3_kernel<<<BSZ, 256>>>(cx, cy, Wp3, bp3, Wlin, blin);
    target_kernel<<<256, 256, smem_t>>>(cx, cy, txp, Wee, bee, Wge, bge, Wat, bat);
    // fps1: relu(z @ Wf1 + b)      (32768,512)x(512,128)
    gemm_kernel<1,0><<<dim3(NTT/128, 2), 256>>>(p_z,   Wf1, bf1, p_fh,  128, 512, 128, 0);
    // fps2: r = fh @ Wf2 + b  -> zd[:,128:384]
    gemm_kernel<0,0><<<dim3(NTT/128, 4), 256>>>(p_fh,  Wf2, bf2, p_zd,  256, 128, 384, 128);
    decgate_kernel<<<NTT/8, 256>>>(Wgd, bgd);
    // decoder MoE: zd2 = sum_e gd_e (zd @ We + be)   (dominant: 19.3 GMAC)
    gemm_kernel<0,1><<<dim3(NTT/128, 6), 256>>>(p_zd,  Wed, bed, p_zd2, 384, 384, 384, 0);
    gemm_kernel<1,0><<<dim3(NTT/128, 4), 256>>>(p_zd2, Wd1, bd1, p_h1,  256, 384, 256, 0);
    gemm_kernel<1,0><<<dim3(NTT/128, 4), 256>>>(p_h1,  Wd2, bd2, p_h2,  256, 256, 256, 0);
    head_kernel<<<NTT/8, 256>>>(Wd3, bd3, out);
    moran_kernel<<<256, 256, smem_m>>>(txp, typ, out);
}

// round 4
// speedup vs baseline: 1.6692x; 1.6692x over previous
#include <cuda_runtime.h>
#include <cuda_bf16.h>
#include <cstdint>
#include <math.h>

#define BSZ 16
#define NC  1024
#define NT  2048
#define NTT (BSZ*NT)
#define XD  8
#define HID 256
#define HH  128
#define DD  384
#define NE  4

// ---------------- scratch ----------------
__device__ float g_enc3[BSZ*HID];
__device__ float g_z  [(size_t)NTT*512];
__device__ float g_fh [(size_t)NTT*HH];
__device__ float g_zd [(size_t)NTT*DD];
__device__ float g_gd [(size_t)NTT*NE];
__device__ float g_zd2[(size_t)NTT*DD];
__device__ float g_h1 [(size_t)NTT*HID];
__device__ float g_h2 [(size_t)NTT*HID];

// bf16 split weights, pre-transposed to [N,K]
__device__ __nv_bfloat16 g_wf1h[128*512], g_wf1l[128*512];
__device__ __nv_bfloat16 g_wf2h[256*128], g_wf2l[256*128];
__device__ __nv_bfloat16 g_wmh [4*384*384], g_wml [4*384*384];
__device__ __nv_bfloat16 g_wd1h[256*384], g_wd1l[256*384];
__device__ __nv_bfloat16 g_wd2h[256*256], g_wd2l[256*256];

__global__ __launch_bounds__(256) void prep_w(
    const float* __restrict__ W, __nv_bfloat16* __restrict__ hi,
    __nv_bfloat16* __restrict__ lo, int K, int N)
{
    int e = blockIdx.y;
    size_t base = (size_t)e*K*N;
    for (int idx = blockIdx.x*256 + threadIdx.x; idx < K*N; idx += gridDim.x*256) {
        int n = idx / K, k = idx - n*K;
        float a = W[base + (size_t)k*N + n];
        __nv_bfloat16 h = __float2bfloat16(a);
        hi[base + idx] = h;
        lo[base + idx] = __float2bfloat16(a - __bfloat162float(h));
    }
}

// ---------------- mma.sync helpers (plain sm_100: HMMA path) ----------------
__device__ __forceinline__ uint32_t smem_u32(const void* p) {
    uint32_t a;
    asm("{ .reg .u64 t; cvta.to.shared.u64 t, %1; cvt.u32.u64 %0, t; }" : "=r"(a) : "l"(p));
    return a;
}
__device__ __forceinline__ void ldm_x4(uint32_t* r, uint32_t addr) {
    asm volatile("ldmatrix.sync.aligned.m8n8.x4.shared.b16 {%0,%1,%2,%3}, [%4];"
        : "=r"(r[0]), "=r"(r[1]), "=r"(r[2]), "=r"(r[3]) : "r"(addr));
}
__device__ __forceinline__ void mma16816(float* d, const uint32_t* a, const uint32_t* b) {
    asm volatile(
        "mma.sync.aligned.m16n8k16.row.col.f32.bf16.bf16.f32 "
        "{%0,%1,%2,%3}, {%4,%5,%6,%7}, {%8,%9}, {%0,%1,%2,%3};"
        : "+f"(d[0]), "+f"(d[1]), "+f"(d[2]), "+f"(d[3])
        : "r"(a[0]), "r"(a[1]), "r"(a[2]), "r"(a[3]), "r"(b[0]), "r"(b[1]));
}
__device__ __forceinline__ void cp16(uint32_t dst, const void* src) {
    asm volatile("cp.async.ca.shared.global [%0], [%1], 16;" :: "r"(dst), "l"(src));
}
__device__ __forceinline__ void cp_commit() { asm volatile("cp.async.commit_group;"); }
__device__ __forceinline__ void cp_wait0()  { asm volatile("cp.async.wait_group 0;"); }

// smem layout: bf16, row stride 40 (80B: 16B-aligned rows, conflict-free ldmatrix)
#define LDS   40
#define TILEB 10240                 // 128*40*2 bytes
#define OFF_AHI(s) ((s)*TILEB)
#define OFF_ALO(s) (20480 + (s)*TILEB)
#define OFF_BHI(s) (40960 + (s)*TILEB)
#define OFF_BLO(s) (61440 + (s)*TILEB)
#define SMEM_GEMM  81920

// C[M,Nfull](@ldc,coff) = act( rowscale(A) @ B^T + bias_eff ); B = [N,K] hi/lo bf16,
// expert-stacked; gate!=null => per-expert row scaling + gated bias, acc over experts.
__global__ __launch_bounds__(256) void mma_gemm(
    const float* __restrict__ A,
    const __nv_bfloat16* __restrict__ Bhi, const __nv_bfloat16* __restrict__ Blo,
    const float* __restrict__ bias, const float* __restrict__ gate,
    float* __restrict__ C,
    int K, int ldc, int coff, int nexp, int relu)
{
    extern __shared__ char smc[];
    __shared__ float sbias[NE*128];
    uint32_t smb = smem_u32(smc);
    int tid = threadIdx.x;
    int lane = tid & 31, warp = tid >> 5;
    int wm = warp >> 2, wn = warp & 3;          // 2x4 warps: 64x32 warp tile
    int m0 = blockIdx.x * 128, n0 = blockIdx.y * 128;
    int Nfull = gridDim.y * 128;
    size_t bstride = (size_t)Nfull * K;

    for (int i = tid; i < nexp*128; i += 256)
        sbias[i] = bias[(size_t)(i >> 7) * Nfull + n0 + (i & 127)];

    float acc[4][4][4];
    #pragma unroll
    for (int mi = 0; mi < 4; mi++)
        #pragma unroll
        for (int ni = 0; ni < 4; ni++)
            #pragma unroll
            for (int q = 0; q < 4; q++) acc[mi][ni][q] = 0.f;

    const int tiles = K >> 5;
    const int T = nexp * tiles;

    // A-prefetch thread mapping: 4 chunks of float4; row = chunk>>3, col=(chunk&7)*4
    int arow[4], acol[4];
    #pragma unroll
    for (int i = 0; i < 4; i++) { int c = tid + i*256; arow[i] = c >> 3; acol[i] = (c & 7) << 2; }
    // B cp.async mapping: 2 chunks of 16B; row = c>>2, col=(c&3)*8
    int brow[2], bcol[2];
    #pragma unroll
    for (int i = 0; i < 2; i++) { int c = tid + i*256; brow[i] = c >> 2; bcol[i] = (c & 3) << 3; }

    float4 ar[4]; float gv[4];

    // ---- prologue: fill stage 0 ----
    {
        int e = 0, k0 = 0;
        #pragma unroll
        for (int i = 0; i < 4; i++) {
            ar[i] = *(const float4*)&A[(size_t)(m0 + arow[i]) * K + k0 + acol[i]];
            gv[i] = gate ? gate[(size_t)(m0 + arow[i]) * 4 + e] : 1.f;
        }
        #pragma unroll
        for (int i = 0; i < 2; i++) {
            uint32_t d = (uint32_t)(brow[i] * LDS + bcol[i]) * 2;
            cp16(smb + OFF_BHI(0) + d, &Bhi[(size_t)(n0 + brow[i]) * K + k0 + bcol[i]]);
            cp16(smb + OFF_BLO(0) + d, &Blo[(size_t)(n0 + brow[i]) * K + k0 + bcol[i]]);
        }
        cp_commit();
        #pragma unroll
        for (int i = 0; i < 4; i++) {
            float4 v = ar[i];
            if (gate) { v.x *= gv[i]; v.y *= gv[i]; v.z *= gv[i]; v.w *= gv[i]; }
            __nv_bfloat162 h01 = __nv_bfloat162(__float2bfloat16(v.x), __float2bfloat16(v.y));
            __nv_bfloat162 h23 = __nv_bfloat162(__float2bfloat16(v.z), __float2bfloat16(v.w));
            __nv_bfloat162 l01 = __nv_bfloat162(
                __float2bfloat16(v.x - __bfloat162float(h01.x)),
                __float2bfloat16(v.y - __bfloat162float(h01.y)));
            __nv_bfloat162 l23 = __nv_bfloat162(
                __float2bfloat16(v.z - __bfloat162float(h23.x)),
                __float2bfloat16(v.w - __bfloat162float(h23.y)));
            int d = arow[i] * LDS + acol[i];
            *(__nv_bfloat162*)(smc + OFF_AHI(0) + d*2)     = h01;
            *(__nv_bfloat162*)(smc + OFF_AHI(0) + d*2 + 4) = h23;
            *(__nv_bfloat162*)(smc + OFF_ALO(0) + d*2)     = l01;
            *(__nv_bfloat162*)(smc + OFF_ALO(0) + d*2 + 4) = l23;
        }
        cp_wait0();
        __syncthreads();
    }

    for (int it = 0; it < T; it++) {
        int s = it & 1, ns = s ^ 1;
        // prefetch it+1
        if (it + 1 < T) {
            int e = (it + 1) / tiles, k0 = ((it + 1) % tiles) << 5;
            #pragma unroll
            for (int i = 0; i < 4; i++) {
                ar[i] = *(const float4*)&A[(size_t)(m0 + arow[i]) * K + k0 + acol[i]];
                gv[i] = gate ? gate[(size_t)(m0 + arow[i]) * 4 + e] : 1.f;
            }
            const __nv_bfloat16* Bh = Bhi + (size_t)e * bstride;
            const __nv_bfloat16* Bl = Blo + (size_t)e * bstride;
            #pragma unroll
            for (int i = 0; i < 2; i++) {
                uint32_t d = (uint32_t)(brow[i] * LDS + bcol[i]) * 2;
                cp16(smb + OFF_BHI(ns) + d, &Bh[(size_t)(n0 + brow[i]) * K + k0 + bcol[i]]);
                cp16(smb + OFF_BLO(ns) + d, &Bl[(size_t)(n0 + brow[i]) * K + k0 + bcol[i]]);
            }
            cp_commit();
        }
        // ---- compute on stage s ----
        uint32_t aH = smb + OFF_AHI(s), aL = smb + OFF_ALO(s);
        uint32_t bH = smb + OFF_BHI(s), bL = smb + OFF_BLO(s);
        #pragma unroll
        for (int ks = 0; ks < 2; ks++) {
            uint32_t bh[4][2], bl[4][2], r4[4];
            #pragma unroll
            for (int np = 0; np < 2; np++) {
                uint32_t off = (uint32_t)((wn*32 + np*16 + (lane & 15)) * LDS
                                          + ks*16 + (lane >> 4)*8) * 2;
                ldm_x4(r4, bH + off);
                bh[np*2+0][0] = r4[0]; bh[np*2+0][1] = r4[2];
                bh[np*2+1][0] = r4[1]; bh[np*2+1][1] = r4[3];
                ldm_x4(r4, bL + off);
                bl[np*2+0][0] = r4[0]; bl[np*2+0][1] = r4[2];
                bl[np*2+1][0] = r4[1]; bl[np*2+1][1] = r4[3];
            }
            uint32_t ah[4][4], al[4][4];
            #pragma unroll
            for (int mi = 0; mi < 4; mi++) {
                uint32_t off = (uint32_t)((wm*64 + mi*16 + (lane & 15)) * LDS
                                          + ks*16 + (lane >> 4)*8) * 2;
                ldm_x4(ah[mi], aH + off);
                ldm_x4(al[mi], aL + off);
            }
            #pragma unroll
            for (int mi = 0; mi < 4; mi++)
                #pragma unroll
                for (int ni = 0; ni < 4; ni++) {
                    mma16816(acc[mi][ni], ah[mi], bh[ni]);
                    mma16816(acc[mi][ni], ah[mi], bl[ni]);
                    mma16816(acc[mi][ni], al[mi], bh[ni]);
                }
        }
        // ---- store prefetched A into stage ns ----
        if (it + 1 < T) {
            #pragma unroll
            for (int i = 0; i < 4; i++) {
                float4 v = ar[i];
                if (gate) { v.x *= gv[i]; v.y *= gv[i]; v.z *= gv[i]; v.w *= gv[i]; }
                __nv_bfloat162 h01 = __nv_bfloat162(__float2bfloat16(v.x), __float2bfloat16(v.y));
                __nv_bfloat162 h23 = __nv_bfloat162(__float2bfloat16(v.z), __float2bfloat16(v.w));
                __nv_bfloat162 l01 = __nv_bfloat162(
                    __float2bfloat16(v.x - __bfloat162float(h01.x)),
                    __float2bfloat16(v.y - __bfloat162float(h01.y)));
                __nv_bfloat162 l23 = __nv_bfloat162(
                    __float2bfloat16(v.z - __bfloat162float(h23.x)),
                    __float2bfloat16(v.w - __bfloat162float(h23.y)));
                int d = arow[i] * LDS + acol[i];
                *(__nv_bfloat162*)(smc + OFF_AHI(ns) + d*2)     = h01;
                *(__nv_bfloat162*)(smc + OFF_AHI(ns) + d*2 + 4) = h23;
                *(__nv_bfloat162*)(smc + OFF_ALO(ns) + d*2)     = l01;
                *(__nv_bfloat162*)(smc + OFF_ALO(ns) + d*2 + 4) = l23;
            }
            cp_wait0();
        }
        __syncthreads();
    }

    // ---- epilogue ----
    #pragma unroll
    for (int mi = 0; mi < 4; mi++) {
        #pragma unroll
        for (int sub = 0; sub < 2; sub++) {
            int row = m0 + wm*64 + mi*16 + (lane >> 2) + sub*8;
            float4 g4 = make_float4(0.f, 0.f, 0.f, 0.f);
            if (gate) g4 = *(const float4*)&gate[(size_t)row * 4];
            #pragma unroll
            for (int ni = 0; ni < 4; ni++) {
                int cl = wn*32 + ni*8 + (lane & 3)*2;
                float be0, be1;
                if (gate) {
                    be0 = g4.x*sbias[cl]     + g4.y*sbias[128+cl]
                        + g4.z*sbias[256+cl] + g4.w*sbias[384+cl];
                    be1 = g4.x*sbias[cl+1]     + g4.y*sbias[128+cl+1]
                        + g4.z*sbias[256+cl+1] + g4.w*sbias[384+cl+1];
                } else { be0 = sbias[cl]; be1 = sbias[cl+1]; }
                float v0 = acc[mi][ni][sub*2+0] + be0;
                float v1 = acc[mi][ni][sub*2+1] + be1;
                if (relu) { v0 = fmaxf(v0, 0.f); v1 = fmaxf(v1, 0.f); }
                *(float2*)&C[(size_t)row * ldc + coff + n0 + cl] = make_float2(v0, v1);
            }
        }
    }
}

// ---------------- enc3 ----------------
__global__ __launch_bounds__(256) void enc3_kernel(
    const float* __restrict__ cx, const float* __restrict__ cy,
    const float* __restrict__ Wp, const float* __restrict__ bp,
    const float* __restrict__ Wl, const float* __restrict__ bl)
{
    __shared__ float red[256*9];
    __shared__ float h0[HID];
    int b = blockIdx.x, tid = threadIdx.x;
    float l[9];
    #pragma unroll
    for (int x = 0; x < 9; x++) l[x] = 0.f;
    for (int c = tid; c < NC; c += 256) {
        #pragma unroll
        for (int x = 0; x < XD; x++) l[x] += cx[((size_t)b*NC + c)*XD + x];
        l[8] += cy[b*NC + c];
    }
    #pragma unroll
    for (int x = 0; x < 9; x++) red[tid*9 + x] = l[x];
    __syncthreads();
    for (int s = 128; s; s >>= 1) {
        if (tid < s) {
            #pragma unroll
            for (int x = 0; x < 9; x++) red[tid*9 + x] += red[(tid+s)*9 + x];
        }
        __syncthreads();
    }
    {
        int h = tid;
        float a = bp[h];
        #pragma unroll
        for (int x = 0; x < 9; x++) a = fmaf(red[x]*(1.f/NC), Wp[x*HID + h], a);
        h0[h] = a;
    }
    __syncthreads();
    {
        int h = tid;
        float a = bl[h];
        for (int k = 0; k < HID; k++) a = fmaf(h0[k], Wl[k*HID + h], a);
        g_enc3[b*HID + h] = a;
    }
}

// ---------------- per-target encoder ----------------
__global__ __launch_bounds__(256) void target_kernel(
    const float* __restrict__ cx, const float* __restrict__ cy,
    const float* __restrict__ txg,
    const float* __restrict__ Wee, const float* __restrict__ bee,
    const float* __restrict__ Wge, const float* __restrict__ bge,
    const float* __restrict__ Wat, const float* __restrict__ bat)
{
    extern __shared__ float smf[];
    float* sc  = smf;
    float* sWe = sc  + NC*9;
    float* sbe = sWe + NE*9*HID;
    float* sWa = sbe + NE*HID;
    float* sba = sWa + XD*HH;
    float* sWg = sba + HH;
    float* sbg = sWg + XD*NE;

    int b  = blockIdx.x >> 4;
    int t0 = (blockIdx.x & 15) << 7;
    int tid = threadIdx.x;

    for (int i = tid; i < NC*XD; i += 256) sc[(i>>3)*9 + (i&7)] = cx[(size_t)b*NC*XD + i];
    for (int i = tid; i < NC;    i += 256) sc[i*9 + 8] = cy[b*NC + i];
    for (int i = tid; i < NE*9*HID; i += 256) sWe[i] = Wee[i];
    for (int i = tid; i < NE*HID;   i += 256) sbe[i] = bee[i];
    for (int i = tid; i < XD*HH;    i += 256) sWa[i] = Wat[i];
    if (tid < HH)    sba[tid] = bat[tid];
    if (tid < XD*NE) sWg[tid] = Wge[tid];
    if (tid < NE)    sbg[tid] = bge[tid];
    __syncthreads();

    int warp = tid >> 5, lane = tid & 31;
    for (int tt = warp; tt < 128; tt += 8) {
        int t = t0 + tt;
        size_t gt = (size_t)b*NT + t;
        float tx[XD];
        #pragma unroll
        for (int x = 0; x < XD; x++) tx[x] = txg[gt*XD + x];

        float acc[10];
        #pragma unroll
        for (int i = 0; i < 10; i++) acc[i] = 0.f;
        for (int c = lane; c < NC; c += 32) {
            const float* p = &sc[c*9];
            float d2 = 1e-12f;
            #pragma unroll
            for (int x = 0; x < XD; x++) { float d = tx[x]-p[x]; d2 = fmaf(d, d, d2); }
            float dist = d2 * __frsqrt_rn(d2);
            float w = __expf(-dist);
            acc[9] += w;
            #pragma unroll
            for (int x = 0; x < 9; x++) acc[x] = fmaf(w, p[x], acc[x]);
        }
        #pragma unroll
        for (int o = 16; o; o >>= 1) {
            #pragma unroll
            for (int i = 0; i < 10; i++) acc[i] += __shfl_xor_sync(0xffffffffu, acc[i], o);
        }
        float inv = 1.f/acc[9];
        float s[9];
        #pragma unroll
        for (int x = 0; x < 9; x++) s[x] = acc[x]*inv;

        float g[NE];
        #pragma unroll
        for (int e = 0; e < NE; e++) {
            float a = sbg[e];
            #pragma unroll
            for (int x = 0; x < XD; x++) a = fmaf(tx[x], sWg[x*NE + e], a);
            g[e] = a;
        }
        float gm = fmaxf(fmaxf(g[0],g[1]), fmaxf(g[2],g[3]));
        float gs = 0.f;
        #pragma unroll
        for (int e = 0; e < NE; e++) { g[e] = __expf(g[e]-gm); gs += g[e]; }
        float gi = 1.f/gs;
        #pragma unroll
        for (int e = 0; e < NE; e++) g[e] *= gi;

        #pragma unroll
        for (int j = 0; j < 8; j++) {
            int h = lane + 32*j;
            float o2 = 0.f;
            #pragma unroll
            for (int e = 0; e < NE; e++) {
                float a = sbe[e*HID + h];
                #pragma unroll
                for (int x = 0; x < 9; x++) a = fmaf(s[x], sWe[(e*9 + x)*HID + h], a);
                o2 = fmaf(g[e], a, o2);
            }
            g_z[gt*512 + 256 + h] = o2;
            g_z[gt*512 + h] = g_enc3[b*HID + h];
        }
        #pragma unroll
        for (int j = 0; j < 4; j++) {
            int h = lane + 32*j;
            float a = sba[h];
            #pragma unroll
            for (int x = 0; x < XD; x++) a = fmaf(tx[x], sWa[x*HH + h], a);
            g_zd[gt*DD + h] = a;
        }
    }
}

// ---------------- decoder gate ----------------
__global__ __launch_bounds__(256) void decgate_kernel(
    const float* __restrict__ Wg, const float* __restrict__ bg)
{
    int warp = threadIdx.x >> 5, lane = threadIdx.x & 31;
    size_t gt = (size_t)blockIdx.x*8 + warp;
    float a0=0.f, a1=0.f, a2=0.f, a3=0.f;
    const float4* W4 = (const float4*)Wg;
    for (int k = lane; k < DD; k += 32) {
        float z = g_zd[gt*DD + k];
        float4 w = W4[k];
        a0 = fmaf(z, w.x, a0); a1 = fmaf(z, w.y, a1);
        a2 = fmaf(z, w.z, a2); a3 = fmaf(z, w.w, a3);
    }
    #pragma unroll
    for (int o = 16; o; o >>= 1) {
        a0 += __shfl_xor_sync(0xffffffffu, a0, o);
        a1 += __shfl_xor_sync(0xffffffffu, a1, o);
        a2 += __shfl_xor_sync(0xffffffffu, a2, o);
        a3 += __shfl_xor_sync(0xffffffffu, a3, o);
    }
    a0 += bg[0]; a1 += bg[1]; a2 += bg[2]; a3 += bg[3];
    float m = fmaxf(fmaxf(a0,a1), fmaxf(a2,a3));
    float e0 = __expf(a0-m), e1 = __expf(a1-m), e2 = __expf(a2-m), e3 = __expf(a3-m);
    float inv = 1.f/(e0+e1+e2+e3);
    if (lane == 0) {
        g_gd[gt*4+0] = e0*inv; g_gd[gt*4+1] = e1*inv;
        g_gd[gt*4+2] = e2*inv; g_gd[gt*4+3] = e3*inv;
    }
}

// ---------------- head ----------------
__global__ __launch_bounds__(256) void head_kernel(
    const float* __restrict__ W3, const float* __restrict__ b3, float* __restrict__ out)
{
    int warp = threadIdx.x >> 5, lane = threadIdx.x & 31;
    size_t gt = (size_t)blockIdx.x*8 + warp;
    float a0=0.f, a1=0.f;
    const float2* W2 = (const float2*)W3;
    for (int k = lane; k < HID; k += 32) {
        float h = g_h2[gt*HID + k];
        float2 w = W2[k];
        a0 = fmaf(h, w.x, a0); a1 = fmaf(h, w.y, a1);
    }
    #pragma unroll
    for (int o = 16; o; o >>= 1) {
        a0 += __shfl_xor_sync(0xffffffffu, a0, o);
        a1 += __shfl_xor_sync(0xffffffffu, a1, o);
    }
    if (lane == 0) {
        float mu = a0 + b3[0];
        float x  = a1 + b3[1];
        float sp = fmaxf(x, 0.f) + log1pf(__expf(-fabsf(x)));
        out[gt]       = mu;
        out[NTT + gt] = 0.1f + 0.9f*sp;
    }
}

// ---------------- Moran k-NN lag ----------------
__global__ __launch_bounds__(256) void moran_kernel(
    const float* __restrict__ txg, const float* __restrict__ tyg, float* __restrict__ out)
{
    extern __shared__ float smf[];
    float* st  = smf;
    float* sy  = st + NT*9;
    float* smu = sy + NT;
    int b  = blockIdx.x >> 4;
    int t0 = (blockIdx.x & 15) << 7;
    int tid = threadIdx.x;

    for (int i = tid; i < NT*XD; i += 256) st[(i>>3)*9 + (i&7)] = txg[(size_t)b*NT*XD + i];
    for (int i = tid; i < NT; i += 256) { sy[i] = tyg[b*NT + i]; smu[i] = out[b*NT + i]; }
    __syncthreads();
    for (int i = tid; i < NT; i += 256) {
        float n = 0.f;
        #pragma unroll
        for (int x = 0; x < XD; x++) { float v = st[i*9 + x]; n = fmaf(v, v, n); }
        st[i*9 + 8] = n;
    }
    __syncthreads();

    int warp = tid >> 5, lane = tid & 31;
    for (int tt = warp; tt < 128; tt += 8) {
        int t = t0 + tt;
        float tx[XD];
        #pragma unroll
        for (int x = 0; x < XD; x++) tx[x] = st[t*9 + x];
        float tn = st[t*9 + 8];

        float bd0=INFINITY,bd1=INFINITY,bd2=INFINITY,bd3=INFINITY,bd4=INFINITY;
        int   bi0=0,bi1=0,bi2=0,bi3=0,bi4=0;
        for (int c = lane; c < NT; c += 32) {
            if (c == t) continue;
            const float* p = &st[c*9];
            float dot = 0.f;
            #pragma unroll
            for (int x = 0; x < XD; x++) dot = fmaf(tx[x], p[x], dot);
            float d2 = tn + p[8] - 2.f*dot;
            d2 = fmaxf(d2, 0.f) + 1e-12f;
            if (d2 < bd4) {
                bd4 = d2; bi4 = c;
                if (bd4 < bd3) { float td=bd3; bd3=bd4; bd4=td; int ti=bi3; bi3=bi4; bi4=ti; }
                if (bd3 < bd2) { float td=bd2; bd2=bd3; bd3=td; int ti=bi2; bi2=bi3; bi3=ti; }
                if (bd2 < bd1) { float td=bd1; bd1=bd2; bd2=td; int ti=bi1; bi1=bi2; bi2=ti; }
                if (bd1 < bd0) { float td=bd0; bd0=bd1; bd1=td; int ti=bi0; bi0=bi1; bi1=ti; }
            }
        }
        float seld[5]; int seli[5];
        #pragma unroll
        for (int r = 0; r < 5; r++) {
            float rd = bd0; int ri = bi0; int rl = lane;
            #pragma unroll
            for (int o = 16; o; o >>= 1) {
                float od = __shfl_xor_sync(0xffffffffu, rd, o);
                int   oi = __shfl_xor_sync(0xffffffffu, ri, o);
                int   ol = __shfl_xor_sync(0xffffffffu, rl, o);
                if (od < rd || (od == rd && oi < ri)) { rd = od; ri = oi; rl = ol; }
            }
            seld[r] = rd; seli[r] = ri;
            if (lane == rl) {
                bd0=bd1; bi0=bi1; bd1=bd2; bi1=bi2; bd2=bd3; bi2=bi3;
                bd3=bd4; bi3=bi4; bd4=INFINITY; bi4=0x7fffffff;
            }
        }
        if (lane == 0) {
            float w[5], ws = 0.f;
            #pragma unroll
            for (int r = 0; r < 5; r++) { w[r] = __expf(-0.1f*sqrtf(seld[r])); ws += w[r]; }
            float inv = 1.f/ws;
            float ly = 0.f, lm = 0.f;
            #pragma unroll
            for (int r = 0; r < 5; r++) {
                float wr = w[r]*inv;
                ly = fmaf(wr, sy[seli[r]],  ly);
                lm = fmaf(wr, smu[seli[r]], lm);
            }
            size_t gt = (size_t)b*NT + t;
            out[2*(size_t)NTT + gt] = ly;
            out[3*(size_t)NTT + gt] = lm;
        }
    }
}

// ---------------- launch ----------------
extern "C" void kernel_launch(void* const* d_in, const int* in_sizes, int n_in,
                              void* d_out, int out_size)
{
    const float* cx   = (const float*)d_in[0];
    const float* cy   = (const float*)d_in[1];
    const float* txp  = (const float*)d_in[2];
    const float* typ  = (const float*)d_in[3];
    const float* Wge  = (const float*)d_in[4];
    const float* bge  = (const float*)d_in[5];
    const float* Wee  = (const float*)d_in[6];
    const float* bee  = (const float*)d_in[7];
    const float* Wp3  = (const float*)d_in[8];
    const float* bp3  = (const float*)d_in[9];
    const float* Wlin = (const float*)d_in[10];
    const float* blin = (const float*)d_in[11];
    const float* Wf1  = (const float*)d_in[12];
    const float* bf1  = (const float*)d_in[13];
    const float* Wf2  = (const float*)d_in[14];
    const float* bf2  = (const float*)d_in[15];
    const float* Wat  = (const float*)d_in[16];
    const float* bat  = (const float*)d_in[17];
    const float* Wgd  = (const float*)d_in[18];
    const float* bgd  = (const float*)d_in[19];
    const float* Wed  = (const float*)d_in[20];
    const float* bed  = (const float*)d_in[21];
    const float* Wd1  = (const float*)d_in[22];
    const float* bd1  = (const float*)d_in[23];
    const float* Wd2  = (const float*)d_in[24];
    const float* bd2  = (const float*)d_in[25];
    const float* Wd3  = (const float*)d_in[26];
    const float* bd3  = (const float*)d_in[27];
    float* out = (float*)d_out;

    float *p_z, *p_fh, *p_zd, *p_zd2, *p_h1, *p_h2, *p_gd;
    cudaGetSymbolAddress((void**)&p_z,   g_z);
    cudaGetSymbolAddress((void**)&p_fh,  g_fh);
    cudaGetSymbolAddress((void**)&p_zd,  g_zd);
    cudaGetSymbolAddress((void**)&p_zd2, g_zd2);
    cudaGetSymbolAddress((void**)&p_h1,  g_h1);
    cudaGetSymbolAddress((void**)&p_h2,  g_h2);
    cudaGetSymbolAddress((void**)&p_gd,  g_gd);
    __nv_bfloat16 *wf1h, *wf1l, *wf2h, *wf2l, *wmh, *wml, *wd1h, *wd1l, *wd2h, *wd2l;
    cudaGetSymbolAddress((void**)&wf1h, g_wf1h); cudaGetSymbolAddress((void**)&wf1l, g_wf1l);
    cudaGetSymbolAddress((void**)&wf2h, g_wf2h); cudaGetSymbolAddress((void**)&wf2l, g_wf2l);
    cudaGetSymbolAddress((void**)&wmh,  g_wmh);  cudaGetSymbolAddress((void**)&wml,  g_wml);
    cudaGetSymbolAddress((void**)&wd1h, g_wd1h); cudaGetSymbolAddress((void**)&wd1l, g_wd1l);
    cudaGetSymbolAddress((void**)&wd2h, g_wd2h); cudaGetSymbolAddress((void**)&wd2l, g_wd2l);

    const int smem_t = (NC*9 + NE*9*HID + NE*HID + XD*HH + HH + XD*NE + NE)*4;
    const int smem_m = (NT*9 + NT + NT)*4;
    cudaFuncSetAttribute(target_kernel, cudaFuncAttributeMaxDynamicSharedMemorySize, smem_t);
    cudaFuncSetAttribute(moran_kernel,  cudaFuncAttributeMaxDynamicSharedMemorySize, smem_m);
    cudaFuncSetAttribute(mma_gemm,      cudaFuncAttributeMaxDynamicSharedMemorySize, SMEM_GEMM);

    prep_w<<<dim3(256,1), 256>>>(Wf1, wf1h, wf1l, 512, 128);
    prep_w<<<dim3(128,1), 256>>>(Wf2, wf2h, wf2l, 128, 256);
    prep_w<<<dim3(576,4), 256>>>(Wed, wmh,  wml,  384, 384);
    prep_w<<<dim3(384,1), 256>>>(Wd1, wd1h, wd1l, 384, 256);
    prep_w<<<dim3(256,1), 256>>>(Wd2, wd2h, wd2l, 256, 256);

    enc3_kernel<<<BSZ, 256>>>(cx, cy, Wp3, bp3, Wlin, blin);
    target_kernel<<<256, 256, smem_t>>>(cx, cy, txp, Wee, bee, Wge, bge, Wat, bat);
    // fps1: relu(z @ Wf1 + b)
    mma_gemm<<<dim3(256,1), 256, SMEM_GEMM>>>(p_z,   wf1h, wf1l, bf1, nullptr, p_fh,  512, 128, 0,   1, 1);
    // fps2: r = fh @ Wf2 + b -> zd[:,128:384]
    mma_gemm<<<dim3(256,2), 256, SMEM_GEMM>>>(p_fh,  wf2h, wf2l, bf2, nullptr, p_zd,  128, 384, 128, 1, 0);
    decgate_kernel<<<NTT/8, 256>>>(Wgd, bgd);
    // decoder MoE (gate-scaled A rows, accumulate over experts)
    mma_gemm<<<dim3(256,3), 256, SMEM_GEMM>>>(p_zd,  wmh,  wml,  bed, p_gd,    p_zd2, 384, 384, 0,   4, 0);
    mma_gemm<<<dim3(256,2), 256, SMEM_GEMM>>>(p_zd2, wd1h, wd1l, bd1, nullptr, p_h1,  384, 256, 0,   1, 1);
    mma_gemm<<<dim3(256,2), 256, SMEM_GEMM>>>(p_h1,  wd2h, wd2l, bd2, nullptr, p_h2,  256, 256, 0,   1, 1);
    head_kernel<<<NTT/8, 256>>>(Wd3, bd3, out);
    moran_kernel<<<256, 256, smem_m>>>(txp, typ, out);
}